// round 4
// baseline (speedup 1.0000x reference)
#include <cuda_runtime.h>

// Fused YOLO decode, single launch.
// Scales 52 & 26 (HW % 2 == 0): one thread per 2 consecutive cells, channel
// reads as float2 (LDG.64), 3 anchors/thread. Scale 13 (HW=169, odd):
// scalar path, 1 cell/thread. Boxes staged via smem -> dense STG.128.
// Output layout: boxes [N,6] in scale order 13,26,52, then mask [N].

#define TPB 128

#define VBLK52 1352  // 128*52*52 cells / 2 / 128
#define VBLK26 338   // 128*26*26 cells / 2 / 128
#define SBLK13 169   // 128*13*13 cells / 128

#define ROWS13 64896      // 21632*3
#define ROWS26 259584     // 86528*3
#define ROWS52 1038336    // 346112*3
#define ROWBASE13 0
#define ROWBASE26 ROWS13
#define ROWBASE52 (ROWS13 + ROWS26)

__device__ __forceinline__ float f2c(const float2& q, int i) {
    return (i == 0) ? q.x : q.y;
}

__global__ __launch_bounds__(TPB)
void decode_fused_kernel(const float* __restrict__ in13,
                         const float* __restrict__ in26,
                         const float* __restrict__ in52,
                         const float* __restrict__ anc13,
                         const float* __restrict__ anc26,
                         const float* __restrict__ anc52,
                         const float* __restrict__ thresh_p,
                         float* __restrict__ boxes,   // [rowsTot, 6]
                         float* __restrict__ mask)    // [rowsTot]
{
    __shared__ float s[2 * TPB * 18];   // 18,432 B

    const int bid = blockIdx.x;
    const int t = threadIdx.x;
    const float thr = __ldg(thresh_p);

    if (bid < VBLK52 + VBLK26) {
        // ---------------- vectorized path (2 cells / thread) ----------------
        const float* in;
        const float* anchors;
        int W, HW;
        float stride;
        int blk;
        size_t rowbase;

        if (bid < VBLK52) {
            in = in52; anchors = anc52; W = 52; HW = 2704; stride = 8.0f;
            blk = bid;          rowbase = ROWBASE52;
        } else {
            in = in26; anchors = anc26; W = 26; HW = 676;  stride = 16.0f;
            blk = bid - VBLK52; rowbase = ROWBASE26;
        }

        const int cell0 = (blk * TPB + t) * 2;     // HW%2==0 -> no batch crossing
        const int b   = cell0 / HW;
        const int cw0 = cell0 - b * HW;
        const int HW2 = HW >> 1;

        const float2* base = (const float2*)(in + (size_t)b * 45 * HW + cw0);

        float fw[2], fh[2];
        #pragma unroll
        for (int i = 0; i < 2; ++i) {
            const int cw = cw0 + i;
            const int h = cw / W;
            fw[i] = (float)(cw - h * W);
            fh[i] = (float)h;
        }

        const float a0w = __ldg(anchors + 0), a0h = __ldg(anchors + 1);
        const float a1w = __ldg(anchors + 2), a1h = __ldg(anchors + 3);
        const float a2w = __ldg(anchors + 4), a2h = __ldg(anchors + 5);

        float m[6];

        #pragma unroll
        for (int a = 0; a < 3; ++a) {
            const float2* p = base + (size_t)(a * 15) * HW2;
            float2 v[15];
            #pragma unroll
            for (int c = 0; c < 15; ++c)
                v[c] = __ldg(p + (size_t)c * HW2);

            const float aw = (a == 0) ? a0w : (a == 1) ? a1w : a2w;
            const float ah = (a == 0) ? a0h : (a == 1) ? a1h : a2h;

            #pragma unroll
            for (int i = 0; i < 2; ++i) {
                const float o0 = f2c(v[0], i);
                const float o1 = f2c(v[1], i);
                const float o2 = f2c(v[2], i);
                const float o3 = f2c(v[3], i);
                const float o4 = f2c(v[4], i);

                float best = f2c(v[5], i);
                int bi = 0;
                #pragma unroll
                for (int c = 1; c < 10; ++c) {
                    const float q = f2c(v[5 + c], i);
                    if (q > best) { best = q; bi = c; }
                }

                const float px = (fw[i] + o1) * stride;
                const float py = (fh[i] + o2) * stride;
                const float pw = aw * __expf(o3);
                const float ph = ah * __expf(o4);

                float* r = s + (t * 2 + i) * 18 + a * 6;
                r[0] = o0;
                r[1] = px - 0.5f * pw;
                r[2] = py - 0.5f * ph;
                r[3] = px + 0.5f * pw;
                r[4] = py + 0.5f * ph;
                r[5] = (float)bi;

                m[i * 3 + a] = (o0 > thr) ? 1.0f : 0.0f;
            }
        }

        // mask: 6 contiguous floats per thread -> 3 STG.64 (8B aligned)
        float2* mp = (float2*)(mask + rowbase + (size_t)blk * TPB * 6 + t * 6);
        mp[0] = make_float2(m[0], m[1]);
        mp[1] = make_float2(m[2], m[3]);
        mp[2] = make_float2(m[4], m[5]);

        __syncthreads();

        // boxes: 4608 floats per CTA = 1152 float4, 9 per thread, coalesced
        float4* ob = (float4*)(boxes + rowbase * 6 + (size_t)blk * TPB * 36);
        const float4* sb = (const float4*)s;
        #pragma unroll
        for (int k = 0; k < 9; ++k)
            ob[k * TPB + t] = sb[k * TPB + t];

    } else {
        // ---------------- scalar path: scale 13 ----------------
        const int blk = bid - (VBLK52 + VBLK26);
        const int HW = 169, W = 13;
        const float stride = 32.0f;

        const int cell = blk * TPB + t;
        const int b  = cell / HW;
        const int cw = cell - b * HW;
        const int h  = cw / W;
        const int w  = cw - h * W;

        const float fw = (float)w;
        const float fh = (float)h;
        const float* base = in13 + (size_t)b * 45 * HW + cw;

        const float a0w = __ldg(anc13 + 0), a0h = __ldg(anc13 + 1);
        const float a1w = __ldg(anc13 + 2), a1h = __ldg(anc13 + 3);
        const float a2w = __ldg(anc13 + 4), a2h = __ldg(anc13 + 5);

        float msk[3];

        #pragma unroll
        for (int a = 0; a < 3; ++a) {
            const float* p = base + (size_t)(a * 15) * HW;
            float c0 = __ldg(p + 0 * (size_t)HW);
            float c1 = __ldg(p + 1 * (size_t)HW);
            float c2 = __ldg(p + 2 * (size_t)HW);
            float c3 = __ldg(p + 3 * (size_t)HW);
            float c4 = __ldg(p + 4 * (size_t)HW);

            float best = __ldg(p + 5 * (size_t)HW);
            int bi = 0;
            #pragma unroll
            for (int c = 1; c < 10; ++c) {
                const float q = __ldg(p + (size_t)(5 + c) * HW);
                if (q > best) { best = q; bi = c; }
            }

            const float px = (fw + c1) * stride;
            const float py = (fh + c2) * stride;
            const float aw = (a == 0) ? a0w : (a == 1) ? a1w : a2w;
            const float ah = (a == 0) ? a0h : (a == 1) ? a1h : a2h;
            const float pw = aw * __expf(c3);
            const float ph = ah * __expf(c4);

            float* r = s + t * 18 + a * 6;
            r[0] = c0;
            r[1] = px - 0.5f * pw;
            r[2] = py - 0.5f * ph;
            r[3] = px + 0.5f * pw;
            r[4] = py + 0.5f * ph;
            r[5] = (float)bi;
            msk[a] = (c0 > thr) ? 1.0f : 0.0f;
        }

        const size_t mrow = (size_t)ROWBASE13 + (size_t)cell * 3;
        mask[mrow + 0] = msk[0];
        mask[mrow + 1] = msk[1];
        mask[mrow + 2] = msk[2];

        __syncthreads();

        float2* ob = (float2*)(boxes + (size_t)ROWBASE13 * 6 + (size_t)blk * TPB * 18);
        const float2* sb = (const float2*)s;
        #pragma unroll
        for (int k = 0; k < 9; ++k)
            ob[k * TPB + t] = sb[k * TPB + t];
    }
}

extern "C" void kernel_launch(void* const* d_in, const int* in_sizes, int n_in,
                              void* d_out, int out_size)
{
    const float* out13 = (const float*)d_in[0];
    const float* out26 = (const float*)d_in[1];
    const float* out52 = (const float*)d_in[2];
    const float* anc13 = (const float*)d_in[3];
    const float* anc26 = (const float*)d_in[4];
    const float* anc52 = (const float*)d_in[5];
    const float* thr   = (const float*)d_in[6];

    float* out = (float*)d_out;
    const int rowsTot = ROWS13 + ROWS26 + ROWS52;   // 1,362,816

    float* boxes = out;                       // [rowsTot, 6]
    float* mask  = out + (size_t)rowsTot * 6; // [rowsTot]

    decode_fused_kernel<<<VBLK52 + VBLK26 + SBLK13, TPB>>>(
        out13, out26, out52, anc13, anc26, anc52, thr, boxes, mask);
}